// round 17
// baseline (speedup 1.0000x reference)
#include <cuda_runtime.h>
#include <cuda_fp16.h>
#include <stdint.h>

typedef unsigned int u32;

#define M_TOT 4096
#define K1    4096
#define N1    11008
#define N2    4096
#define SROWB 144                   // bytes per smem row: 64 halves (128B) + 16B pad
#define STAGEB (128 * SROWB)        // bytes per stage per array (18432 B)
#define NTHREADS 512

// scratch: fp16 x; h = silu(g)*u stored fp16
__device__ __half g_xh[(size_t)M_TOT * K1];
__device__ __half g_hh[(size_t)M_TOT * N1];

// ---------------------------------------------------------------------------
// helpers
// ---------------------------------------------------------------------------
static __device__ __forceinline__ u32 s2u(const void* p){
    u32 a; asm("{ .reg .u64 t; cvta.to.shared.u64 t, %1; cvt.u32.u64 %0, t; }":"=r"(a):"l"(p)); return a;
}
static __device__ __forceinline__ float silu_f(float g){ return g / (1.f + __expf(-g)); }

// D(f16) += A(16x16) * B(16x8), fp16 operands, fp16 accumulate (2-reg C/D)
static __device__ __forceinline__ void mma16h(u32* d, const u32* a, const u32* b){
    asm volatile("mma.sync.aligned.m16n8k16.row.col.f16.f16.f16.f16 "
        "{%0,%1}, {%2,%3,%4,%5}, {%6,%7}, {%0,%1};"
        : "+r"(d[0]), "+r"(d[1])
        : "r"(a[0]), "r"(a[1]), "r"(a[2]), "r"(a[3]), "r"(b[0]), "r"(b[1]));
}
// merge f16x2 pair into 4 fp32 accumulators
static __device__ __forceinline__ void merge2(float* acc, u32 h0, u32 h1){
    float2 f0 = __half22float2(*(__half2*)&h0);
    float2 f1 = __half22float2(*(__half2*)&h1);
    acc[0] += f0.x; acc[1] += f0.y; acc[2] += f1.x; acc[3] += f1.y;
}
static __device__ __forceinline__ void ldsm4(u32 addr, u32* r){
    asm volatile("ldmatrix.sync.aligned.m8n8.x4.shared.b16 {%0,%1,%2,%3}, [%4];"
        : "=r"(r[0]), "=r"(r[1]), "=r"(r[2]), "=r"(r[3]) : "r"(addr));
}
static __device__ __forceinline__ void cpa16(u32 dst, const void* src){
    asm volatile("cp.async.cg.shared.global [%0], [%1], 16;" :: "r"(dst), "l"(src));
}
static __device__ __forceinline__ void cpcommit(){ asm volatile("cp.async.commit_group;" ::: "memory"); }
static __device__ __forceinline__ void cpwait0(){ asm volatile("cp.async.wait_group 0;" ::: "memory"); }

// dequant one packed int32 (8 int4 ascending k) -> 8 fp16 (16B), one STS.128
static __device__ __forceinline__ void deq8h(u32 q, float s, float nzt, void* dst){
    __half2 h[4];
    h[0] = __floats2half2_rn(fmaf((float)( q        & 15), s, nzt),
                             fmaf((float)((q >>  4) & 15), s, nzt));
    h[1] = __floats2half2_rn(fmaf((float)((q >>  8) & 15), s, nzt),
                             fmaf((float)((q >> 12) & 15), s, nzt));
    h[2] = __floats2half2_rn(fmaf((float)((q >> 16) & 15), s, nzt),
                             fmaf((float)((q >> 20) & 15), s, nzt));
    h[3] = __floats2half2_rn(fmaf((float)((q >> 24) & 15), s, nzt),
                             fmaf((float)((q >> 28) & 15), s, nzt));
    *(uint4*)dst = *(const uint4*)h;
}

// ---------------------------------------------------------------------------
// Kernel 0: convert x to fp16 (8 floats -> 8 halves per thread)
// ---------------------------------------------------------------------------
__global__ void cvtx_k(const float* __restrict__ x){
    size_t i = (size_t)blockIdx.x * blockDim.x + threadIdx.x;
    float4 v0 = ((const float4*)x)[i * 2];
    float4 v1 = ((const float4*)x)[i * 2 + 1];
    __half2 h[4];
    h[0] = __floats2half2_rn(v0.x, v0.y);
    h[1] = __floats2half2_rn(v0.z, v0.w);
    h[2] = __floats2half2_rn(v1.x, v1.y);
    h[3] = __floats2half2_rn(v1.z, v1.w);
    ((uint4*)g_xh)[i] = *(const uint4*)h;
}

// ---------------------------------------------------------------------------
// Kernel A: fused gate+up GEMM (M=4096,K=4096,N=11008) + silu*mul -> g_hh
// CTA 128x128, BK=64, 2-stage, 16 warps = 4(M) x 4(N), warp tile 32x32 dual.
// f16-accumulate HMMA in K=32 chunks, merged into fp32 accumulators.
// ---------------------------------------------------------------------------
#define GU_SMEM (3 * 2 * STAGEB)   // 110592 B

__global__ __launch_bounds__(NTHREADS, 1)
void gateup_mma(const int* __restrict__ gqw, const float* __restrict__ gsc, const int* __restrict__ gqz,
                const int* __restrict__ uqw, const float* __restrict__ usc, const int* __restrict__ uqz)
{
    extern __shared__ char smc[];
    char* A0 = smc;
    char* G0 = smc + 2 * STAGEB;
    char* U0 = smc + 4 * STAGEB;
    const u32 sbA = s2u(A0), sbG = s2u(G0), sbU = s2u(U0);

    const int tid = threadIdx.x, wid = tid >> 5, lid = tid & 31;
    const int warpM = wid >> 2, warpN = wid & 3;
    const int n0 = blockIdx.x * 128, m0 = blockIdx.y * 128;
    const int r = lid >> 2, c = lid & 3;

    const __half* xbase = g_xh + (size_t)m0 * K1;
    const int bn = tid & 127, kr = (tid >> 7) * 2;
    const int gcol = n0 + bn, zsh = (bn & 7) * 4;

    const int g8 = lid >> 3, lr = lid & 7;
    u32 almA[2];
#pragma unroll
    for (int mt = 0; mt < 2; mt++){
        int row = warpM * 32 + mt * 16 + (g8 & 1) * 8 + lr;
        almA[mt] = sbA + (u32)(row * SROWB) + (u32)((g8 >> 1) * 16);
    }
    const int bnrow = (lid & 7) + ((lid >> 4) & 1) * 8;
    const int bkseg = (lid >> 3) & 1;
    u32 almG[2], almU[2];
#pragma unroll
    for (int p = 0; p < 2; p++){
        int row = warpN * 32 + p * 16 + bnrow;
        almG[p] = sbG + (u32)(row * SROWB) + (u32)(bkseg * 16);
        almU[p] = sbU + (u32)(row * SROWB) + (u32)(bkseg * 16);
    }

    float accG[2][4][4], accU[2][4][4];
#pragma unroll
    for (int i = 0; i < 2; i++)
#pragma unroll
        for (int j = 0; j < 4; j++)
#pragma unroll
            for (int k = 0; k < 4; k++){ accG[i][j][k] = 0.f; accU[i][j][k] = 0.f; }

    const int NK = K1 / 64;   // 64
    u32 gq[2], uq[2], gz, uz; float gs, us;

#define ACOPY_GU(st, kt1) do {                                                   \
    u32 so_ = sbA + (u32)((st) * STAGEB);                                        \
    _Pragma("unroll")                                                            \
    for (int i_ = 0; i_ < 2; i_++){                                              \
        int id_ = tid + i_ * NTHREADS, row_ = id_ >> 3, seg_ = id_ & 7;          \
        cpa16(so_ + (u32)(row_ * SROWB + seg_ * 16),                             \
              xbase + (size_t)row_ * K1 + (size_t)(kt1) * 64 + seg_ * 8);        \
    }                                                                            \
    cpcommit();                                                                  \
} while (0)

#define WLOAD_GU(kt1) do {                                                       \
    size_t wr_ = (size_t)((kt1) * 8 + kr) * N1 + gcol;                           \
    _Pragma("unroll")                                                            \
    for (int w_ = 0; w_ < 2; w_++){                                              \
        gq[w_] = __ldg((const u32*)gqw + wr_ + (size_t)w_ * N1);                 \
        uq[w_] = __ldg((const u32*)uqw + wr_ + (size_t)w_ * N1);                 \
    }                                                                            \
    int grp_ = (kt1) >> 1;                                                       \
    gs = __ldg(gsc + (size_t)grp_ * N1 + gcol);                                  \
    us = __ldg(usc + (size_t)grp_ * N1 + gcol);                                  \
    gz = __ldg((const u32*)gqz + (size_t)grp_ * (N1 / 8) + (gcol >> 3));         \
    uz = __ldg((const u32*)uqz + (size_t)grp_ * (N1 / 8) + (gcol >> 3));         \
} while (0)

#define WSTORE_GU(st) do {                                                       \
    char* gd_ = G0 + (st) * STAGEB + bn * SROWB + kr * 16;                       \
    float nz_ = -((float)(((gz >> zsh) & 15) + 1)) * gs;                         \
    _Pragma("unroll")                                                            \
    for (int w_ = 0; w_ < 2; w_++) deq8h(gq[w_], gs, nz_, gd_ + w_ * 16);        \
    char* ud_ = U0 + (st) * STAGEB + bn * SROWB + kr * 16;                       \
    nz_ = -((float)(((uz >> zsh) & 15) + 1)) * us;                               \
    _Pragma("unroll")                                                            \
    for (int w_ = 0; w_ < 2; w_++) deq8h(uq[w_], us, nz_, ud_ + w_ * 16);        \
} while (0)

    // prologue: stage 0
    ACOPY_GU(0, 0);
    WLOAD_GU(0);
    WSTORE_GU(0);
    cpwait0();
    __syncthreads();

    for (int kt = 0; kt < NK; ++kt){
        const int cur = kt & 1, nxt = cur ^ 1;
        if (kt + 1 < NK){
            ACOPY_GU(nxt, kt + 1);
            WLOAD_GU(kt + 1);
        }

        const u32 so = (u32)(cur * STAGEB);
#pragma unroll
        for (int jp = 0; jp < 2; jp++){       // K=32 chunk = 2 x k16
            u32 af[2][2][4], bg[2][2][4], bu[2][2][4];
#pragma unroll
            for (int mt = 0; mt < 2; mt++)
#pragma unroll
                for (int jj = 0; jj < 2; jj++)
                    ldsm4(almA[mt] + so + (jp * 2 + jj) * 32, af[mt][jj]);
#pragma unroll
            for (int p = 0; p < 2; p++)
#pragma unroll
                for (int jj = 0; jj < 2; jj++){
                    ldsm4(almG[p] + so + (jp * 2 + jj) * 32, bg[p][jj]);
                    ldsm4(almU[p] + so + (jp * 2 + jj) * 32, bu[p][jj]);
                }
#pragma unroll
            for (int mt = 0; mt < 2; mt++)
#pragma unroll
                for (int nt = 0; nt < 4; nt++){
                    u32 hg[2] = {0u, 0u}, hu[2] = {0u, 0u};
#pragma unroll
                    for (int jj = 0; jj < 2; jj++){
                        mma16h(hg, af[mt][jj], &bg[nt >> 1][jj][(nt & 1) * 2]);
                        mma16h(hu, af[mt][jj], &bu[nt >> 1][jj][(nt & 1) * 2]);
                    }
                    merge2(accG[mt][nt], hg[0], hg[1]);
                    merge2(accU[mt][nt], hu[0], hu[1]);
                }
        }

        if (kt + 1 < NK){
            WSTORE_GU(nxt);
            cpwait0();
        }
        __syncthreads();
    }
#undef ACOPY_GU
#undef WLOAD_GU
#undef WSTORE_GU

    // epilogue: h = silu(g) * u -> fp16
#pragma unroll
    for (int mt = 0; mt < 2; mt++)
#pragma unroll
        for (int nt = 0; nt < 4; nt++){
            const int row = m0 + warpM * 32 + mt * 16 + r;
            const int col = n0 + warpN * 32 + nt * 8 + c * 2;
            __half* hp = g_hh + (size_t)row * N1 + col;
            const float* a = accG[mt][nt]; const float* b = accU[mt][nt];
            *(__half2*)hp            = __floats2half2_rn(silu_f(a[0]) * b[0], silu_f(a[1]) * b[1]);
            *(__half2*)(hp + 8 * N1) = __floats2half2_rn(silu_f(a[2]) * b[2], silu_f(a[3]) * b[3]);
        }
}

// ---------------------------------------------------------------------------
// Kernel B: down GEMM out = h @ Wd (M=4096, K=11008, N=4096), BK=64, f16 acc
// ---------------------------------------------------------------------------
#define DN_SMEM (2 * 2 * STAGEB)   // 73728 B

__global__ __launch_bounds__(NTHREADS, 1)
void down_mma(const int* __restrict__ dqw, const float* __restrict__ dsc,
              const int* __restrict__ dqz, float* __restrict__ out)
{
    extern __shared__ char smc[];
    char* A0 = smc;
    char* B0 = smc + 2 * STAGEB;
    const u32 sbA = s2u(A0), sbB = s2u(B0);

    const int tid = threadIdx.x, wid = tid >> 5, lid = tid & 31;
    const int warpM = wid >> 2, warpN = wid & 3;
    const int n0 = blockIdx.x * 128, m0 = blockIdx.y * 128;
    const int r = lid >> 2, c = lid & 3;

    const __half* xbase = g_hh + (size_t)m0 * N1;
    const int bn = tid & 127, kr = (tid >> 7) * 2;
    const int gcol = n0 + bn, zsh = (bn & 7) * 4;

    const int g8 = lid >> 3, lr = lid & 7;
    u32 almA[2];
#pragma unroll
    for (int mt = 0; mt < 2; mt++){
        int row = warpM * 32 + mt * 16 + (g8 & 1) * 8 + lr;
        almA[mt] = sbA + (u32)(row * SROWB) + (u32)((g8 >> 1) * 16);
    }
    const int bnrow = (lid & 7) + ((lid >> 4) & 1) * 8;
    const int bkseg = (lid >> 3) & 1;
    u32 almB[2];
#pragma unroll
    for (int p = 0; p < 2; p++){
        int row = warpN * 32 + p * 16 + bnrow;
        almB[p] = sbB + (u32)(row * SROWB) + (u32)(bkseg * 16);
    }

    float acc[2][4][4];
#pragma unroll
    for (int i = 0; i < 2; i++)
#pragma unroll
        for (int j = 0; j < 4; j++)
#pragma unroll
            for (int k = 0; k < 4; k++) acc[i][j][k] = 0.f;

    const int NK = N1 / 64;   // 172
    u32 dq[2], dz; float ds;

#define ACOPY_DN(st, kt1) do {                                                   \
    u32 so_ = sbA + (u32)((st) * STAGEB);                                        \
    _Pragma("unroll")                                                            \
    for (int i_ = 0; i_ < 2; i_++){                                              \
        int id_ = tid + i_ * NTHREADS, row_ = id_ >> 3, seg_ = id_ & 7;          \
        cpa16(so_ + (u32)(row_ * SROWB + seg_ * 16),                             \
              xbase + (size_t)row_ * N1 + (size_t)(kt1) * 64 + seg_ * 8);        \
    }                                                                            \
    cpcommit();                                                                  \
} while (0)

#define WLOAD_DN(kt1) do {                                                       \
    size_t wr_ = (size_t)((kt1) * 8 + kr) * N2 + gcol;                           \
    _Pragma("unroll")                                                            \
    for (int w_ = 0; w_ < 2; w_++)                                               \
        dq[w_] = __ldg((const u32*)dqw + wr_ + (size_t)w_ * N2);                 \
    int grp_ = (kt1) >> 1;                                                       \
    ds = __ldg(dsc + (size_t)grp_ * N2 + gcol);                                  \
    dz = __ldg((const u32*)dqz + (size_t)grp_ * (N2 / 8) + (gcol >> 3));         \
} while (0)

#define WSTORE_DN(st) do {                                                       \
    char* bd_ = B0 + (st) * STAGEB + bn * SROWB + kr * 16;                       \
    float nz_ = -((float)(((dz >> zsh) & 15) + 1)) * ds;                         \
    _Pragma("unroll")                                                            \
    for (int w_ = 0; w_ < 2; w_++) deq8h(dq[w_], ds, nz_, bd_ + w_ * 16);        \
} while (0)

    ACOPY_DN(0, 0);
    WLOAD_DN(0);
    WSTORE_DN(0);
    cpwait0();
    __syncthreads();

    for (int kt = 0; kt < NK; ++kt){
        const int cur = kt & 1, nxt = cur ^ 1;
        if (kt + 1 < NK){
            ACOPY_DN(nxt, kt + 1);
            WLOAD_DN(kt + 1);
        }

        const u32 so = (u32)(cur * STAGEB);
#pragma unroll
        for (int jp = 0; jp < 2; jp++){
            u32 af[2][2][4], bf[2][2][4];
#pragma unroll
            for (int mt = 0; mt < 2; mt++)
#pragma unroll
                for (int jj = 0; jj < 2; jj++)
                    ldsm4(almA[mt] + so + (jp * 2 + jj) * 32, af[mt][jj]);
#pragma unroll
            for (int p = 0; p < 2; p++)
#pragma unroll
                for (int jj = 0; jj < 2; jj++)
                    ldsm4(almB[p] + so + (jp * 2 + jj) * 32, bf[p][jj]);
#pragma unroll
            for (int mt = 0; mt < 2; mt++)
#pragma unroll
                for (int nt = 0; nt < 4; nt++){
                    u32 hd[2] = {0u, 0u};
#pragma unroll
                    for (int jj = 0; jj < 2; jj++)
                        mma16h(hd, af[mt][jj], &bf[nt >> 1][jj][(nt & 1) * 2]);
                    merge2(acc[mt][nt], hd[0], hd[1]);
                }
        }

        if (kt + 1 < NK){
            WSTORE_DN(nxt);
            cpwait0();
        }
        __syncthreads();
    }
#undef ACOPY_DN
#undef WLOAD_DN
#undef WSTORE_DN

#pragma unroll
    for (int mt = 0; mt < 2; mt++)
#pragma unroll
        for (int nt = 0; nt < 4; nt++){
            const int row = m0 + warpM * 32 + mt * 16 + r;
            const int col = n0 + warpN * 32 + nt * 8 + c * 2;
            float* op = out + (size_t)row * N2 + col;
            const float* a = acc[mt][nt];
            *(float2*)op            = make_float2(a[0], a[1]);
            *(float2*)(op + 8 * N2) = make_float2(a[2], a[3]);
        }
}

// ---------------------------------------------------------------------------
// Host launcher
// ---------------------------------------------------------------------------
extern "C" void kernel_launch(void* const* d_in, const int* in_sizes, int n_in,
                              void* d_out, int out_size)
{
    (void)in_sizes; (void)n_in; (void)out_size;
    const float* x   = (const float*)d_in[0];
    const int*   gqw = (const int*)  d_in[1];
    const float* gsc = (const float*)d_in[2];
    const int*   gqz = (const int*)  d_in[3];
    const int*   uqw = (const int*)  d_in[4];
    const float* usc = (const float*)d_in[5];
    const int*   uqz = (const int*)  d_in[6];
    const int*   dqw = (const int*)  d_in[7];
    const float* dsc = (const float*)d_in[8];
    const int*   dqz = (const int*)  d_in[9];
    float* out = (float*)d_out;

    cudaFuncSetAttribute(gateup_mma, cudaFuncAttributeMaxDynamicSharedMemorySize, GU_SMEM);
    cudaFuncSetAttribute(down_mma,   cudaFuncAttributeMaxDynamicSharedMemorySize, DN_SMEM);

    cvtx_k<<<(int)((size_t)M_TOT * K1 / 8 / 256), 256>>>(x);

    dim3 gridA(N1 / 128, M_TOT / 128);   // 86 x 32
    gateup_mma<<<gridA, NTHREADS, GU_SMEM>>>(gqw, gsc, gqz, uqw, usc, uqz);

    dim3 gridB(N2 / 128, M_TOT / 128);   // 32 x 32
    down_mma<<<gridB, NTHREADS, DN_SMEM>>>(dqw, dsc, dqz, out);
}